// round 8
// baseline (speedup 1.0000x reference)
#include <cuda_runtime.h>
#include <math.h>

// Shapes fixed: x (4,64,128,128), k (4,64,25,25), alpha (1,64,1,1), sf=2.
// Output (4,64,256,256) fp32.
#define NPLANES 256
#define NCH 64
#define HSTRIDE (129 * 256)   // half-spectrum plane stride (rows 0..128)

__device__ float2 g_SA[NPLANES * HSTRIDE];     // FB half
__device__ float2 g_SB[NPLANES * HSTRIDE];     // G half
__device__ float2 g_SC[NPLANES * 128 * 128];   // Rf, then Fx^T
__device__ float2 g_tw[256];                   // e^{-2*pi*i t/256}

__global__ void k_twinit() {
    int t = threadIdx.x;
    float s, c;
    sincospif(-(float)t * (1.0f / 128.0f), &s, &c);
    g_tw[t] = make_float2(c, s);
}

#define SP(i) ((i) + ((i) >> 4))

__device__ __forceinline__ float2 cmulf(float2 a, float2 b) {
    return make_float2(a.x * b.x - a.y * b.y, a.x * b.y + a.y * b.x);
}

template <bool INV>
__device__ __forceinline__ float2 twmul(float2 a, float2 w) {
    float wy = INV ? -w.y : w.y;
    return make_float2(a.x * w.x - a.y * wy, a.x * wy + a.y * w.x);
}

template <bool INV>
__device__ __forceinline__ void bfly4(float2 v[4]) {
    float2 t0 = make_float2(v[0].x + v[2].x, v[0].y + v[2].y);
    float2 t1 = make_float2(v[0].x - v[2].x, v[0].y - v[2].y);
    float2 t2 = make_float2(v[1].x + v[3].x, v[1].y + v[3].y);
    float2 t3 = make_float2(v[1].x - v[3].x, v[1].y - v[3].y);
    v[0] = make_float2(t0.x + t2.x, t0.y + t2.y);
    v[2] = make_float2(t0.x - t2.x, t0.y - t2.y);
    if (!INV) {
        v[1] = make_float2(t1.x + t3.y, t1.y - t3.x);
        v[3] = make_float2(t1.x - t3.y, t1.y + t3.x);
    } else {
        v[1] = make_float2(t1.x - t3.y, t1.y + t3.x);
        v[3] = make_float2(t1.x + t3.y, t1.y - t3.x);
    }
}

// ---------------------------------------------------------------------------
// N=256 radix-4 Stockham; lane = 64 threads (2 warps) -> __syncthreads.
// ---------------------------------------------------------------------------
template <bool INV>
__device__ __forceinline__ void fft256_core(float2 v[4], float2* s0, float2* s1,
                                            int t, const float2* tw) {
    bfly4<INV>(v);
    s0[SP(4 * t + 0)] = v[0]; s0[SP(4 * t + 1)] = v[1];
    s0[SP(4 * t + 2)] = v[2]; s0[SP(4 * t + 3)] = v[3];
    __syncthreads();
    {
        int jm = t & 3;
        v[0] = s0[SP(t)];       v[1] = s0[SP(t + 64)];
        v[2] = s0[SP(t + 128)]; v[3] = s0[SP(t + 192)];
        v[1] = twmul<INV>(v[1], tw[16 * jm]);
        v[2] = twmul<INV>(v[2], tw[32 * jm]);
        v[3] = twmul<INV>(v[3], tw[48 * jm]);
        bfly4<INV>(v);
        int d = 4 * (t - jm) + jm;
        s1[SP(d)] = v[0]; s1[SP(d + 4)] = v[1];
        s1[SP(d + 8)] = v[2]; s1[SP(d + 12)] = v[3];
    }
    __syncthreads();
    {
        int jm = t & 15;
        v[0] = s1[SP(t)];       v[1] = s1[SP(t + 64)];
        v[2] = s1[SP(t + 128)]; v[3] = s1[SP(t + 192)];
        v[1] = twmul<INV>(v[1], tw[4 * jm]);
        v[2] = twmul<INV>(v[2], tw[8 * jm]);
        v[3] = twmul<INV>(v[3], tw[12 * jm]);
        bfly4<INV>(v);
        int d = 4 * (t - jm) + jm;
        s0[SP(d)] = v[0]; s0[SP(d + 16)] = v[1];
        s0[SP(d + 32)] = v[2]; s0[SP(d + 48)] = v[3];
    }
    __syncthreads();
    {
        v[0] = s0[SP(t)];       v[1] = s0[SP(t + 64)];
        v[2] = s0[SP(t + 128)]; v[3] = s0[SP(t + 192)];
        v[1] = twmul<INV>(v[1], tw[t]);
        v[2] = twmul<INV>(v[2], tw[2 * t]);
        v[3] = twmul<INV>(v[3], tw[3 * t]);
        bfly4<INV>(v);
    }
}

// ---------------------------------------------------------------------------
// N=128 radix-4x3 + radix-2; lane = exactly one warp -> __syncwarp only.
// ---------------------------------------------------------------------------
template <bool INV>
__device__ __forceinline__ void fft128_core(float2 v[4], float2* s0, float2* s1,
                                            int t, const float2* tw) {
    bfly4<INV>(v);
    s0[SP(4 * t + 0)] = v[0]; s0[SP(4 * t + 1)] = v[1];
    s0[SP(4 * t + 2)] = v[2]; s0[SP(4 * t + 3)] = v[3];
    __syncwarp();
    {
        int jm = t & 3;
        v[0] = s0[SP(t)];      v[1] = s0[SP(t + 32)];
        v[2] = s0[SP(t + 64)]; v[3] = s0[SP(t + 96)];
        v[1] = twmul<INV>(v[1], tw[16 * jm]);
        v[2] = twmul<INV>(v[2], tw[32 * jm]);
        v[3] = twmul<INV>(v[3], tw[48 * jm]);
        bfly4<INV>(v);
        int d = 4 * (t - jm) + jm;
        s1[SP(d)] = v[0]; s1[SP(d + 4)] = v[1];
        s1[SP(d + 8)] = v[2]; s1[SP(d + 12)] = v[3];
    }
    __syncwarp();
    {
        int jm = t & 15;
        v[0] = s1[SP(t)];      v[1] = s1[SP(t + 32)];
        v[2] = s1[SP(t + 64)]; v[3] = s1[SP(t + 96)];
        v[1] = twmul<INV>(v[1], tw[4 * jm]);
        v[2] = twmul<INV>(v[2], tw[8 * jm]);
        v[3] = twmul<INV>(v[3], tw[12 * jm]);
        bfly4<INV>(v);
        int d = 4 * (t - jm) + jm;
        s0[SP(d)] = v[0]; s0[SP(d + 16)] = v[1];
        s0[SP(d + 32)] = v[2]; s0[SP(d + 48)] = v[3];
    }
    __syncwarp();
    {
        float2 a0 = s0[SP(t)],      b0 = s0[SP(t + 64)];
        float2 a1 = s0[SP(t + 32)], b1 = s0[SP(t + 96)];
        float2 bw0 = twmul<INV>(b0, tw[2 * t]);
        float2 bw1 = twmul<INV>(b1, tw[2 * (t + 32)]);
        v[0] = make_float2(a0.x + bw0.x, a0.y + bw0.y);
        v[2] = make_float2(a0.x - bw0.x, a0.y - bw0.y);
        v[1] = make_float2(a1.x + bw1.x, a1.y + bw1.y);
        v[3] = make_float2(a1.x - bw1.x, a1.y - bw1.y);
    }
}

// ---------------------------------------------------------------------------
// FB step A: row FFTs (N=256) of the 25 nonzero otf rows per plane -> Rf (SC).
// ---------------------------------------------------------------------------
__global__ void k_fbrows(const float* __restrict__ psf, float2* __restrict__ Rf) {
    __shared__ float2 sbuf[8][2 * 272];
    __shared__ float2 stw[256];
    int t = threadIdx.x, ry = threadIdx.y;   // (64,8)
    int lt = ry * 64 + t;
    if (lt < 256) stw[lt] = g_tw[lt];
    int gr = blockIdx.x * 8 + ry;
    int p = gr / 25, r = gr - p * 25;
    const float* kp = psf + p * 625 + r * 25;
    float2 v[4];
#pragma unroll
    for (int q = 0; q < 4; ++q) {
        int c = (t + 64 * q + 12) & 255;
        v[q] = make_float2(c < 25 ? kp[c] : 0.f, 0.f);
    }
    __syncthreads();
    fft256_core<false>(v, sbuf[ry], sbuf[ry] + 272, t, stw);
    float2* d = Rf + gr * 256;
    d[t] = v[0]; d[t + 64] = v[1]; d[t + 128] = v[2]; d[t + 192] = v[3];
}

// ---------------------------------------------------------------------------
// FB step B: 25-term direct column DFT -> FB^T rows 0..128 ONLY (Hermitian).
// ---------------------------------------------------------------------------
__global__ void k_fbcol(const float2* __restrict__ Rf, float2* __restrict__ FBt) {
    __shared__ float2 sRf[25][32];
    __shared__ float2 stw[256];
    int p = blockIdx.y;
    int u0 = blockIdx.x * 32;
    int v = threadIdx.x;
    stw[v] = g_tw[v];
    for (int e = v; e < 800; e += 256) {
        int r = e >> 5, uu = e & 31;
        sRf[r][uu] = Rf[p * 6400 + r * 256 + u0 + uu];
    }
    __syncthreads();

    float2 twr[25];
#pragma unroll
    for (int r = 0; r < 25; ++r)
        twr[r] = stw[(v * (r - 12)) & 255];

#pragma unroll 2
    for (int u = 0; u < 32; ++u) {
        int ug = u0 + u;
        if (ug > 128) break;
        float2 acc = make_float2(0.f, 0.f);
#pragma unroll
        for (int r = 0; r < 25; ++r) {
            float2 a = sRf[r][u];
            acc.x += a.x * twr[r].x - a.y * twr[r].y;
            acc.y += a.x * twr[r].y + a.y * twr[r].x;
        }
        FBt[p * HSTRIDE + ug * 256 + v] = acc;
    }
}

// ---------------------------------------------------------------------------
// FUSED per-plane 2D FFT of x: row FFTs (paired real rows) into an
// XOR-swizzled 128KB smem tile, then column FFTs, writing Fx^T[p][u][vh].
// Tile element (y,u) lives at word index y*128 + (u ^ (y & 31)).
// One block per plane, 1024 threads (32 warps) for occupancy.
// ---------------------------------------------------------------------------
__global__ void __launch_bounds__(1024, 1)
k_xfft2(const float* __restrict__ x, float2* __restrict__ Fx) {
    extern __shared__ float2 tile[];          // 128*128 float2 = 128KB dynamic
    __shared__ float2 sbuf[32][2 * 136];
    __shared__ float2 stw[256];
    int t = threadIdx.x;                      // 0..31
    int w = threadIdx.y;                      // 0..31
    int tid = w * 32 + t;
    if (tid < 256) stw[tid] = g_tw[tid];
    __syncthreads();

    int p = blockIdx.x;
    const float* xp = x + p * 16384;

    // Phase 1: 64 paired row FFTs (pairs j = w + 32*it)
#pragma unroll
    for (int it = 0; it < 2; ++it) {
        int j = w + 32 * it;                  // pair id 0..63
        const float* xa = xp + j * 256;
        float2 v[4];
#pragma unroll
        for (int q = 0; q < 4; ++q)
            v[q] = make_float2(xa[t + 32 * q], xa[128 + t + 32 * q]);
        fft128_core<false>(v, sbuf[w], sbuf[w] + 136, t, stw);
        float2* s0 = sbuf[w];
#pragma unroll
        for (int q = 0; q < 4; ++q) s0[SP(t + 32 * q)] = v[q];
        __syncwarp();
        int ya = 2 * j, yb = 2 * j + 1;
        int sa = ya & 31, sb = yb & 31;
#pragma unroll
        for (int q = 0; q < 4; ++q) {
            int k = t + 32 * q;
            float2 Zk = s0[SP(k)];
            float2 Zm = s0[SP((128 - k) & 127)];
            tile[ya * 128 + (k ^ sa)] =
                make_float2(0.5f * (Zk.x + Zm.x), 0.5f * (Zk.y - Zm.y));
            tile[yb * 128 + (k ^ sb)] =
                make_float2(0.5f * (Zk.y + Zm.y), 0.5f * (Zm.x - Zk.x));
        }
        __syncwarp();
    }
    __syncthreads();

    // Phase 2: 128 column FFTs (u = w + 32*rep), write Fx^T[u][vh]
    float2* Fp = Fx + p * 16384;
#pragma unroll
    for (int rep = 0; rep < 4; ++rep) {
        int u = w + 32 * rep;
        float2 v[4];
#pragma unroll
        for (int q = 0; q < 4; ++q) {
            int y = t + 32 * q;
            v[q] = tile[y * 128 + (u ^ (y & 31))];
        }
        fft128_core<false>(v, sbuf[w], sbuf[w] + 136, t, stw);
        float2* d = Fp + u * 128;
        d[t] = v[0]; d[t + 32] = v[1]; d[t + 64] = v[2]; d[t + 96] = v[3];
    }
}

// ---------------------------------------------------------------------------
// FUSED solve + inverse-256: one spectrum row A (width-freq) per 64 threads.
// ---------------------------------------------------------------------------
__global__ void k_solve(const float* __restrict__ alpha) {
    __shared__ float2 sbuf[8][2 * 272];
    __shared__ float2 stw[256];
    int t = threadIdx.x, ry = threadIdx.y;     // (64,8)
    int lt = ry * 64 + t;
    if (lt < 256) stw[lt] = g_tw[lt];
    __syncthreads();

    int p = blockIdx.y;
    int A = blockIdx.x * 8 + ry;               // 0..135; rows >128 idle-write
    int AA = A <= 128 ? A : 128;
    bool hi = (AA == 128);
    int vv = hi ? 0 : AA;

    float a = alpha[p & (NCH - 1)];
    float be = 1.f / (1.f + expf(9.f - a)) + 1e-3f;
    float ibe = 1.f / be;

    const float2* FBp = g_SA + p * HSTRIDE;
    const float2* FBd = FBp + vv * 256;
    const float2* FBm = FBp + (128 - vv) * 256;
    const float2* Fxr = g_SC + (p << 14) + (vv << 7);

    float2 twv0 = stw[vv], twv1 = stw[vv + 128];
    float2 pv0 = make_float2(1.f + twv0.x, twv0.y);
    float2 pv1 = make_float2(1.f + twv1.x, twv1.y);

    float2 v[4];
#pragma unroll
    for (int half = 0; half < 2; ++half) {
        int u = t + 64 * half;
        float2 fx = Fxr[u];

        float2 FB[4];
        FB[0] = FBd[u];
        FB[1] = FBd[u + 128];
        if (vv == 0) {
            FB[2] = FBm[u];
            FB[3] = FBm[u + 128];
        } else {
            float2 t0 = FBm[(256 - u) & 255];
            float2 t1 = FBm[128 - u];
            FB[2] = make_float2(t0.x, -t0.y);
            FB[3] = make_float2(t1.x, -t1.y);
        }

        float2 twu0 = stw[u], twu1 = stw[u + 128];
        float2 pu0 = make_float2(1.f + twu0.x, twu0.y);
        float2 pu1 = make_float2(1.f + twu1.x, twu1.y);

        float2 FR[4];
        float2 sBR = make_float2(0.f, 0.f);
        float sW = 0.f;
#pragma unroll
        for (int q = 0; q < 4; ++q) {
            float2 fb = FB[q];
            float2 P = cmulf((q & 1) ? pu1 : pu0, (q >> 1) ? pv1 : pv0);
            float2 m = make_float2(fb.x + be * P.x, -fb.y + be * P.y);
            float2 fr = cmulf(fx, m);
            FR[q] = fr;
            sBR.x += fb.x * fr.x - fb.y * fr.y;
            sBR.y += fb.x * fr.y + fb.y * fr.x;
            sW += fb.x * fb.x + fb.y * fb.y;
        }
        sBR.x *= 0.25f; sBR.y *= 0.25f; sW *= 0.25f;
        float inv = 1.f / (sW + be);
        float2 iw = make_float2(sBR.x * inv, sBR.y * inv);

        int qlo = hi ? 2 : 0;
#pragma unroll
        for (int j = 0; j < 2; ++j) {
            int q = qlo + j;
            float2 tmp = make_float2(FB[q].x * iw.x + FB[q].y * iw.y,
                                     FB[q].x * iw.y - FB[q].y * iw.x);
            float2 Q = make_float2((FR[q].x - tmp.x) * ibe,
                                   (FR[q].y - tmp.y) * ibe);
            v[half + 2 * j] = Q;
        }
    }

    fft256_core<true>(v, sbuf[ry], sbuf[ry] + 272, t, stw);

    if (A <= 128) {
        float2* d = g_SB + p * HSTRIDE + A * 256;
        d[t] = v[0]; d[t + 64] = v[1]; d[t + 128] = v[2]; d[t + 192] = v[3];
    }
}

// ---------------------------------------------------------------------------
// Final: fused transpose + Hermitian-packed real inverse along width.
// ---------------------------------------------------------------------------
__global__ void k_final(const float2* __restrict__ G, float2* __restrict__ out2) {
    __shared__ float2 tile[129][17];
    __shared__ float2 sbuf[8][2 * 136];
    __shared__ float2 stw[256];
    int t = threadIdx.x, f = threadIdx.y;
    int tid = f * 32 + t;
    stw[tid] = g_tw[tid];
    int p = blockIdx.y, x0 = blockIdx.x * 16;
    const float2* Gp = G + p * HSTRIDE;
#pragma unroll
    for (int it = 0; it < 9; ++it) {
        int idx = it * 256 + tid;
        int A = idx >> 4, ff = idx & 15;
        if (A < 129) tile[A][ff] = Gp[A * 256 + x0 + ff];
    }
    __syncthreads();
    const float s = 1.0f / 65536.0f;
#pragma unroll
    for (int rep = 0; rep < 2; ++rep) {
        int fc = f + 8 * rep;
        float2 v[4];
#pragma unroll
        for (int q = 0; q < 4; ++q) {
            int k = t + 32 * q;
            float2 hk = tile[k][fc];
            float2 hm = tile[128 - k][fc];
            float2 c = stw[k];
            float Ax = hk.x + hm.x, Ay = hk.y - hm.y;
            float Bx = hk.x - hm.x, By = hk.y + hm.y;
            float cr = c.x * Bx + c.y * By;
            float ci = c.x * By - c.y * Bx;
            v[q] = make_float2(Ax - ci, Ay + cr);
        }
        fft128_core<true>(v, sbuf[f], sbuf[f] + 136, t, stw);
        float2* d = out2 + ((p << 8) + x0 + fc) * 128;
#pragma unroll
        for (int q = 0; q < 4; ++q)
            d[t + 32 * q] = make_float2(v[q].x * s, v[q].y * s);
    }
}

extern "C" void kernel_launch(void* const* d_in, const int* in_sizes, int n_in,
                              void* d_out, int out_size) {
    const float* x     = (const float*)d_in[0];
    const float* psf   = (const float*)d_in[1];
    const float* alpha = (const float*)d_in[2];
    float* out = (float*)d_out;

    float2 *SA, *SB, *SC;
    cudaGetSymbolAddress((void**)&SA, g_SA);
    cudaGetSymbolAddress((void**)&SB, g_SB);
    cudaGetSymbolAddress((void**)&SC, g_SC);

    k_twinit<<<1, 256>>>();

    // FB^T half (rows 0..128) -> SA
    k_fbrows<<<800, dim3(64, 8)>>>(psf, SC);
    k_fbcol<<<dim3(5, NPLANES), 256>>>(SC, SA);

    // Fx^T[p][u][vh] -> SC  (single fused per-plane 2D FFT, 32 warps/block)
    cudaFuncSetAttribute(k_xfft2, cudaFuncAttributeMaxDynamicSharedMemorySize,
                         128 * 128 * sizeof(float2));
    k_xfft2<<<NPLANES, dim3(32, 32), 128 * 128 * sizeof(float2)>>>(x, SC);

    // FUSED solve + inverse-256 -> SB holds G half (rows 0..128)
    k_solve<<<dim3(17, NPLANES), dim3(64, 8)>>>(alpha);

    // Hermitian-packed real inverse along width -> out
    k_final<<<dim3(16, NPLANES), dim3(32, 8)>>>(SB, (float2*)out);
}

// round 9
// speedup vs baseline: 1.0672x; 1.0672x over previous
#include <cuda_runtime.h>
#include <math.h>

// Shapes fixed: x (4,64,128,128), k (4,64,25,25), alpha (1,64,1,1), sf=2.
// Output (4,64,256,256) fp32.
#define NPLANES 256
#define NCH 64
#define HSTRIDE (129 * 256)   // half-spectrum plane stride (rows 0..128)

__device__ float2 g_SA[NPLANES * HSTRIDE];     // FB half
__device__ float2 g_SB[NPLANES * HSTRIDE];     // G half
__device__ float2 g_SC[NPLANES * 128 * 128];   // Fx^T

#define SP(i) ((i) + ((i) >> 4))

// in-kernel twiddle: stw[i] = e^{-2 pi i t/256}
__device__ __forceinline__ float2 twval(int t) {
    float s, c;
    sincospif(-(float)t * (1.0f / 128.0f), &s, &c);
    return make_float2(c, s);
}

__device__ __forceinline__ float2 cmulf(float2 a, float2 b) {
    return make_float2(a.x * b.x - a.y * b.y, a.x * b.y + a.y * b.x);
}

template <bool INV>
__device__ __forceinline__ float2 twmul(float2 a, float2 w) {
    float wy = INV ? -w.y : w.y;
    return make_float2(a.x * w.x - a.y * wy, a.x * wy + a.y * w.x);
}

template <bool INV>
__device__ __forceinline__ void bfly4(float2 v[4]) {
    float2 t0 = make_float2(v[0].x + v[2].x, v[0].y + v[2].y);
    float2 t1 = make_float2(v[0].x - v[2].x, v[0].y - v[2].y);
    float2 t2 = make_float2(v[1].x + v[3].x, v[1].y + v[3].y);
    float2 t3 = make_float2(v[1].x - v[3].x, v[1].y - v[3].y);
    v[0] = make_float2(t0.x + t2.x, t0.y + t2.y);
    v[2] = make_float2(t0.x - t2.x, t0.y - t2.y);
    if (!INV) {
        v[1] = make_float2(t1.x + t3.y, t1.y - t3.x);
        v[3] = make_float2(t1.x - t3.y, t1.y + t3.x);
    } else {
        v[1] = make_float2(t1.x - t3.y, t1.y + t3.x);
        v[3] = make_float2(t1.x + t3.y, t1.y - t3.x);
    }
}

// ---------------------------------------------------------------------------
// N=256 radix-4 Stockham; lane = 64 threads (2 warps) -> __syncthreads.
// ---------------------------------------------------------------------------
template <bool INV>
__device__ __forceinline__ void fft256_core(float2 v[4], float2* s0, float2* s1,
                                            int t, const float2* tw) {
    bfly4<INV>(v);
    s0[SP(4 * t + 0)] = v[0]; s0[SP(4 * t + 1)] = v[1];
    s0[SP(4 * t + 2)] = v[2]; s0[SP(4 * t + 3)] = v[3];
    __syncthreads();
    {
        int jm = t & 3;
        v[0] = s0[SP(t)];       v[1] = s0[SP(t + 64)];
        v[2] = s0[SP(t + 128)]; v[3] = s0[SP(t + 192)];
        v[1] = twmul<INV>(v[1], tw[16 * jm]);
        v[2] = twmul<INV>(v[2], tw[32 * jm]);
        v[3] = twmul<INV>(v[3], tw[48 * jm]);
        bfly4<INV>(v);
        int d = 4 * (t - jm) + jm;
        s1[SP(d)] = v[0]; s1[SP(d + 4)] = v[1];
        s1[SP(d + 8)] = v[2]; s1[SP(d + 12)] = v[3];
    }
    __syncthreads();
    {
        int jm = t & 15;
        v[0] = s1[SP(t)];       v[1] = s1[SP(t + 64)];
        v[2] = s1[SP(t + 128)]; v[3] = s1[SP(t + 192)];
        v[1] = twmul<INV>(v[1], tw[4 * jm]);
        v[2] = twmul<INV>(v[2], tw[8 * jm]);
        v[3] = twmul<INV>(v[3], tw[12 * jm]);
        bfly4<INV>(v);
        int d = 4 * (t - jm) + jm;
        s0[SP(d)] = v[0]; s0[SP(d + 16)] = v[1];
        s0[SP(d + 32)] = v[2]; s0[SP(d + 48)] = v[3];
    }
    __syncthreads();
    {
        v[0] = s0[SP(t)];       v[1] = s0[SP(t + 64)];
        v[2] = s0[SP(t + 128)]; v[3] = s0[SP(t + 192)];
        v[1] = twmul<INV>(v[1], tw[t]);
        v[2] = twmul<INV>(v[2], tw[2 * t]);
        v[3] = twmul<INV>(v[3], tw[3 * t]);
        bfly4<INV>(v);
    }
}

// ---------------------------------------------------------------------------
// N=128 radix-4x3 + radix-2; lane = exactly one warp -> __syncwarp only.
// ---------------------------------------------------------------------------
template <bool INV>
__device__ __forceinline__ void fft128_core(float2 v[4], float2* s0, float2* s1,
                                            int t, const float2* tw) {
    bfly4<INV>(v);
    s0[SP(4 * t + 0)] = v[0]; s0[SP(4 * t + 1)] = v[1];
    s0[SP(4 * t + 2)] = v[2]; s0[SP(4 * t + 3)] = v[3];
    __syncwarp();
    {
        int jm = t & 3;
        v[0] = s0[SP(t)];      v[1] = s0[SP(t + 32)];
        v[2] = s0[SP(t + 64)]; v[3] = s0[SP(t + 96)];
        v[1] = twmul<INV>(v[1], tw[16 * jm]);
        v[2] = twmul<INV>(v[2], tw[32 * jm]);
        v[3] = twmul<INV>(v[3], tw[48 * jm]);
        bfly4<INV>(v);
        int d = 4 * (t - jm) + jm;
        s1[SP(d)] = v[0]; s1[SP(d + 4)] = v[1];
        s1[SP(d + 8)] = v[2]; s1[SP(d + 12)] = v[3];
    }
    __syncwarp();
    {
        int jm = t & 15;
        v[0] = s1[SP(t)];      v[1] = s1[SP(t + 32)];
        v[2] = s1[SP(t + 64)]; v[3] = s1[SP(t + 96)];
        v[1] = twmul<INV>(v[1], tw[4 * jm]);
        v[2] = twmul<INV>(v[2], tw[8 * jm]);
        v[3] = twmul<INV>(v[3], tw[12 * jm]);
        bfly4<INV>(v);
        int d = 4 * (t - jm) + jm;
        s0[SP(d)] = v[0]; s0[SP(d + 16)] = v[1];
        s0[SP(d + 32)] = v[2]; s0[SP(d + 48)] = v[3];
    }
    __syncwarp();
    {
        float2 a0 = s0[SP(t)],      b0 = s0[SP(t + 64)];
        float2 a1 = s0[SP(t + 32)], b1 = s0[SP(t + 96)];
        float2 bw0 = twmul<INV>(b0, tw[2 * t]);
        float2 bw1 = twmul<INV>(b1, tw[2 * (t + 32)]);
        v[0] = make_float2(a0.x + bw0.x, a0.y + bw0.y);
        v[2] = make_float2(a0.x - bw0.x, a0.y - bw0.y);
        v[1] = make_float2(a1.x + bw1.x, a1.y + bw1.y);
        v[3] = make_float2(a1.x - bw1.x, a1.y - bw1.y);
    }
}

// ---------------------------------------------------------------------------
// FUSED FB: per-plane. Phase 1: 25 row FFTs (N=256) of rolled PSF rows into
// smem Rf. Phase 2: 25-term direct column DFT -> FB^T rows 0..128 (Hermitian).
// Block (64,8) = 512 threads; 2 blocks/SM.
// ---------------------------------------------------------------------------
__global__ void __launch_bounds__(512, 2)
k_fb(const float* __restrict__ psf, float2* __restrict__ FBt) {
    __shared__ float2 Rf[25][256];
    __shared__ float2 sbuf[8][2 * 272];
    __shared__ float2 stw[256];
    int t = threadIdx.x;      // 0..63
    int g = threadIdx.y;      // 0..7
    int tid = g * 64 + t;
    if (tid < 256) stw[tid] = twval(tid);
    __syncthreads();

    int p = blockIdx.x;
    // Phase 1: rows r = g + 8*it, it=0..3 (r<25 guard; all groups run the FFT)
#pragma unroll
    for (int it = 0; it < 4; ++it) {
        int r = g + 8 * it;
        int rr = r < 25 ? r : 24;
        const float* kp = psf + p * 625 + rr * 25;
        float2 v[4];
#pragma unroll
        for (int q = 0; q < 4; ++q) {
            int c = (t + 64 * q + 12) & 255;
            v[q] = make_float2(c < 25 ? kp[c] : 0.f, 0.f);
        }
        fft256_core<false>(v, sbuf[g], sbuf[g] + 272, t, stw);
        if (r < 25) {
            Rf[r][t] = v[0]; Rf[r][t + 64] = v[1];
            Rf[r][t + 128] = v[2]; Rf[r][t + 192] = v[3];
        }
    }
    __syncthreads();

    // Phase 2: FB^T[u][v] = sum_r Rf[r][u] * tw[(v*(r-12)) mod 256]
    int v = tid & 255;        // height-freq (contiguous in output)
    int uc = tid >> 8;        // 0..1
    float2 twr[25];
#pragma unroll
    for (int r = 0; r < 25; ++r)
        twr[r] = stw[(v * (r - 12)) & 255];
    float2* Fp = FBt + p * HSTRIDE;
    for (int u = uc; u <= 128; u += 2) {
        float2 acc = make_float2(0.f, 0.f);
#pragma unroll
        for (int r = 0; r < 25; ++r) {
            float2 a = Rf[r][u];
            acc.x += a.x * twr[r].x - a.y * twr[r].y;
            acc.y += a.x * twr[r].y + a.y * twr[r].x;
        }
        Fp[u * 256 + v] = acc;
    }
}

// ---------------------------------------------------------------------------
// FUSED per-plane 2D FFT of x: row FFTs (paired real rows) into an
// XOR-swizzled 128KB smem tile, then column FFTs, writing Fx^T[p][u][vh].
// Tile element (y,u) lives at word index y*128 + (u ^ (y & 31)).
// ---------------------------------------------------------------------------
__global__ void __launch_bounds__(1024, 1)
k_xfft2(const float* __restrict__ x, float2* __restrict__ Fx) {
    extern __shared__ float2 tile[];          // 128*128 float2 = 128KB dynamic
    __shared__ float2 sbuf[32][2 * 136];
    __shared__ float2 stw[256];
    int t = threadIdx.x;                      // 0..31
    int w = threadIdx.y;                      // 0..31
    int tid = w * 32 + t;
    if (tid < 256) stw[tid] = twval(tid);
    __syncthreads();

    int p = blockIdx.x;
    const float* xp = x + p * 16384;

    // Phase 1: 64 paired row FFTs (pairs j = w + 32*it)
#pragma unroll
    for (int it = 0; it < 2; ++it) {
        int j = w + 32 * it;                  // pair id 0..63
        const float* xa = xp + j * 256;
        float2 v[4];
#pragma unroll
        for (int q = 0; q < 4; ++q)
            v[q] = make_float2(xa[t + 32 * q], xa[128 + t + 32 * q]);
        fft128_core<false>(v, sbuf[w], sbuf[w] + 136, t, stw);
        float2* s0 = sbuf[w];
#pragma unroll
        for (int q = 0; q < 4; ++q) s0[SP(t + 32 * q)] = v[q];
        __syncwarp();
        int ya = 2 * j, yb = 2 * j + 1;
        int sa = ya & 31, sb = yb & 31;
#pragma unroll
        for (int q = 0; q < 4; ++q) {
            int k = t + 32 * q;
            float2 Zk = s0[SP(k)];
            float2 Zm = s0[SP((128 - k) & 127)];
            tile[ya * 128 + (k ^ sa)] =
                make_float2(0.5f * (Zk.x + Zm.x), 0.5f * (Zk.y - Zm.y));
            tile[yb * 128 + (k ^ sb)] =
                make_float2(0.5f * (Zk.y + Zm.y), 0.5f * (Zm.x - Zk.x));
        }
        __syncwarp();
    }
    __syncthreads();

    // Phase 2: 128 column FFTs (u = w + 32*rep), write Fx^T[u][vh]
    float2* Fp = Fx + p * 16384;
#pragma unroll
    for (int rep = 0; rep < 4; ++rep) {
        int u = w + 32 * rep;
        float2 v[4];
#pragma unroll
        for (int q = 0; q < 4; ++q) {
            int y = t + 32 * q;
            v[q] = tile[y * 128 + (u ^ (y & 31))];
        }
        fft128_core<false>(v, sbuf[w], sbuf[w] + 136, t, stw);
        float2* d = Fp + u * 128;
        d[t] = v[0]; d[t + 32] = v[1]; d[t + 64] = v[2]; d[t + 96] = v[3];
    }
}

// ---------------------------------------------------------------------------
// FUSED solve + inverse-256: one spectrum row A (width-freq) per 64 threads.
// ---------------------------------------------------------------------------
__global__ void k_solve(const float* __restrict__ alpha) {
    __shared__ float2 sbuf[8][2 * 272];
    __shared__ float2 stw[256];
    int t = threadIdx.x, ry = threadIdx.y;     // (64,8)
    int lt = ry * 64 + t;
    if (lt < 256) stw[lt] = twval(lt);
    __syncthreads();

    int p = blockIdx.y;
    int A = blockIdx.x * 8 + ry;               // 0..135; rows >128 idle-write
    int AA = A <= 128 ? A : 128;
    bool hi = (AA == 128);
    int vv = hi ? 0 : AA;

    float a = alpha[p & (NCH - 1)];
    float be = 1.f / (1.f + expf(9.f - a)) + 1e-3f;
    float ibe = 1.f / be;

    const float2* FBp = g_SA + p * HSTRIDE;
    const float2* FBd = FBp + vv * 256;
    const float2* FBm = FBp + (128 - vv) * 256;
    const float2* Fxr = g_SC + (p << 14) + (vv << 7);

    float2 twv0 = stw[vv], twv1 = stw[vv + 128];
    float2 pv0 = make_float2(1.f + twv0.x, twv0.y);
    float2 pv1 = make_float2(1.f + twv1.x, twv1.y);

    float2 v[4];
#pragma unroll
    for (int half = 0; half < 2; ++half) {
        int u = t + 64 * half;
        float2 fx = Fxr[u];

        float2 FB[4];
        FB[0] = FBd[u];
        FB[1] = FBd[u + 128];
        if (vv == 0) {
            FB[2] = FBm[u];
            FB[3] = FBm[u + 128];
        } else {
            float2 t0 = FBm[(256 - u) & 255];
            float2 t1 = FBm[128 - u];
            FB[2] = make_float2(t0.x, -t0.y);
            FB[3] = make_float2(t1.x, -t1.y);
        }

        float2 twu0 = stw[u], twu1 = stw[u + 128];
        float2 pu0 = make_float2(1.f + twu0.x, twu0.y);
        float2 pu1 = make_float2(1.f + twu1.x, twu1.y);

        float2 FR[4];
        float2 sBR = make_float2(0.f, 0.f);
        float sW = 0.f;
#pragma unroll
        for (int q = 0; q < 4; ++q) {
            float2 fb = FB[q];
            float2 P = cmulf((q & 1) ? pu1 : pu0, (q >> 1) ? pv1 : pv0);
            float2 m = make_float2(fb.x + be * P.x, -fb.y + be * P.y);
            float2 fr = cmulf(fx, m);
            FR[q] = fr;
            sBR.x += fb.x * fr.x - fb.y * fr.y;
            sBR.y += fb.x * fr.y + fb.y * fr.x;
            sW += fb.x * fb.x + fb.y * fb.y;
        }
        sBR.x *= 0.25f; sBR.y *= 0.25f; sW *= 0.25f;
        float inv = 1.f / (sW + be);
        float2 iw = make_float2(sBR.x * inv, sBR.y * inv);

        int qlo = hi ? 2 : 0;
#pragma unroll
        for (int j = 0; j < 2; ++j) {
            int q = qlo + j;
            float2 tmp = make_float2(FB[q].x * iw.x + FB[q].y * iw.y,
                                     FB[q].x * iw.y - FB[q].y * iw.x);
            float2 Q = make_float2((FR[q].x - tmp.x) * ibe,
                                   (FR[q].y - tmp.y) * ibe);
            v[half + 2 * j] = Q;
        }
    }

    fft256_core<true>(v, sbuf[ry], sbuf[ry] + 272, t, stw);

    if (A <= 128) {
        float2* d = g_SB + p * HSTRIDE + A * 256;
        d[t] = v[0]; d[t + 64] = v[1]; d[t + 128] = v[2]; d[t + 192] = v[3];
    }
}

// ---------------------------------------------------------------------------
// Final: fused transpose + Hermitian-packed real inverse along width.
// ---------------------------------------------------------------------------
__global__ void k_final(const float2* __restrict__ G, float2* __restrict__ out2) {
    __shared__ float2 tile[129][17];
    __shared__ float2 sbuf[8][2 * 136];
    __shared__ float2 stw[256];
    int t = threadIdx.x, f = threadIdx.y;      // (32,8)
    int tid = f * 32 + t;
    stw[tid] = twval(tid);
    int p = blockIdx.y, x0 = blockIdx.x * 16;
    const float2* Gp = G + p * HSTRIDE;
#pragma unroll
    for (int it = 0; it < 9; ++it) {
        int idx = it * 256 + tid;
        int A = idx >> 4, ff = idx & 15;
        if (A < 129) tile[A][ff] = Gp[A * 256 + x0 + ff];
    }
    __syncthreads();
    const float s = 1.0f / 65536.0f;
#pragma unroll
    for (int rep = 0; rep < 2; ++rep) {
        int fc = f + 8 * rep;
        float2 v[4];
#pragma unroll
        for (int q = 0; q < 4; ++q) {
            int k = t + 32 * q;
            float2 hk = tile[k][fc];
            float2 hm = tile[128 - k][fc];
            float2 c = stw[k];
            float Ax = hk.x + hm.x, Ay = hk.y - hm.y;
            float Bx = hk.x - hm.x, By = hk.y + hm.y;
            float cr = c.x * Bx + c.y * By;
            float ci = c.x * By - c.y * Bx;
            v[q] = make_float2(Ax - ci, Ay + cr);
        }
        fft128_core<true>(v, sbuf[f], sbuf[f] + 136, t, stw);
        float2* d = out2 + ((p << 8) + x0 + fc) * 128;
#pragma unroll
        for (int q = 0; q < 4; ++q)
            d[t + 32 * q] = make_float2(v[q].x * s, v[q].y * s);
    }
}

extern "C" void kernel_launch(void* const* d_in, const int* in_sizes, int n_in,
                              void* d_out, int out_size) {
    const float* x     = (const float*)d_in[0];
    const float* psf   = (const float*)d_in[1];
    const float* alpha = (const float*)d_in[2];
    float* out = (float*)d_out;

    float2 *SA, *SB, *SC;
    cudaGetSymbolAddress((void**)&SA, g_SA);
    cudaGetSymbolAddress((void**)&SB, g_SB);
    cudaGetSymbolAddress((void**)&SC, g_SC);

    // 1) FB^T half (rows 0..128) -> SA  (fused rows+col, per plane)
    k_fb<<<NPLANES, dim3(64, 8)>>>(psf, SA);

    // 2) Fx^T[p][u][vh] -> SC  (fused per-plane 2D FFT)
    cudaFuncSetAttribute(k_xfft2, cudaFuncAttributeMaxDynamicSharedMemorySize,
                         128 * 128 * sizeof(float2));
    k_xfft2<<<NPLANES, dim3(32, 32), 128 * 128 * sizeof(float2)>>>(x, SC);

    // 3) FUSED solve + inverse-256 -> SB holds G half (rows 0..128)
    k_solve<<<dim3(17, NPLANES), dim3(64, 8)>>>(alpha);

    // 4) Hermitian-packed real inverse along width -> out  (measured by ncu)
    k_final<<<dim3(16, NPLANES), dim3(32, 8)>>>(SB, (float2*)out);
}